// round 13
// baseline (speedup 1.0000x reference)
#include <cuda_runtime.h>

#define IMG_H 1080
#define IMG_W 1920
#define TILE_W 128
#define TILE_H 8
#define RW (TILE_W + 4)   // 132 region cols (halo 2 each side)
#define RH (TILE_H + 4)   // 12 region rows
#define NPLANE (RH * RW)  // 1584 floats per plane

__global__ __launch_bounds__(256)
void jbf_kernel(const float* __restrict__ tpl,
                const float* __restrict__ vec,
                float* __restrict__ out)
{
    __shared__ float sT0[NPLANE];
    __shared__ float sT1[NPLANE];
    __shared__ float sT2[NPLANE];
    __shared__ float sV0[NPLANE];
    __shared__ float sV1[NPLANE];

    const int tx = threadIdx.x;          // 0..31
    const int ty = threadIdx.y;          // 0..7
    const int tid = ty * 32 + tx;        // 0..255
    const int x0 = blockIdx.x * TILE_W;
    const int y0 = blockIdx.y * TILE_H;

    const float* __restrict__ t0 = tpl;
    const float* __restrict__ t1 = tpl + IMG_H * IMG_W;
    const float* __restrict__ t2 = tpl + 2 * IMG_H * IMG_W;
    const float* __restrict__ v0 = vec;
    const float* __restrict__ v1 = vec + IMG_H * IMG_W;

    // ---- cooperative fill of the haloed region (zero-pad OOB) ----
    #pragma unroll 7
    for (int i = tid; i < NPLANE; i += 256) {
        int rr = i / RW;
        int cc = i - rr * RW;
        int gy = y0 - 2 + rr;
        int gx = x0 - 2 + cc;
        bool inb = ((unsigned)gy < IMG_H) && ((unsigned)gx < IMG_W);
        int g = inb ? (gy * IMG_W + gx) : 0;
        sT0[i] = inb ? __ldg(t0 + g) : 0.0f;
        sT1[i] = inb ? __ldg(t1 + g) : 0.0f;
        sT2[i] = inb ? __ldg(t2 + g) : 0.0f;
        sV0[i] = inb ? __ldg(v0 + g) : 0.0f;
        sV1[i] = inb ? __ldg(v1 + g) : 0.0f;
    }
    __syncthreads();

    // ---- each thread computes 4 consecutive output pixels ----
    const int bcol = tx * 4;                 // smem base col of 8-float window
    const int ccol = bcol + 2;               // smem col of first center pixel

    float c0[4], c1[4], c2[4];
    #pragma unroll
    for (int p = 0; p < 4; p++) {
        int s = (ty + 2) * RW + ccol + p;
        c0[p] = sT0[s];
        c1[p] = sT1[s];
        c2[p] = sT2[s];
    }

    float num0[4] = {0.f, 0.f, 0.f, 0.f};
    float num1[4] = {0.f, 0.f, 0.f, 0.f};
    float den[4]  = {0.f, 0.f, 0.f, 0.f};

    #pragma unroll
    for (int r = 0; r < 5; r++) {            // tap row: dy = r - 2
        const int base = (ty + r) * RW + bcol;

        float a[8], b[8], c[8], va[8], vb[8];
        *(float4*)&a[0]  = *(const float4*)&sT0[base];
        *(float4*)&a[4]  = *(const float4*)&sT0[base + 4];
        *(float4*)&b[0]  = *(const float4*)&sT1[base];
        *(float4*)&b[4]  = *(const float4*)&sT1[base + 4];
        *(float4*)&c[0]  = *(const float4*)&sT2[base];
        *(float4*)&c[4]  = *(const float4*)&sT2[base + 4];
        *(float4*)&va[0] = *(const float4*)&sV0[base];
        *(float4*)&va[4] = *(const float4*)&sV0[base + 4];
        *(float4*)&vb[0] = *(const float4*)&sV1[base];
        *(float4*)&vb[4] = *(const float4*)&sV1[base + 4];

        #pragma unroll
        for (int dx = 0; dx < 5; dx++) {
            #pragma unroll
            for (int p = 0; p < 4; p++) {
                const int j = dx + p;
                float d0 = c0[p] - a[j];
                float d1 = c1[p] - b[j];
                float d2 = c2[p] - c[j];
                float d  = d0 * d0;
                d = fmaf(d1, d1, d);
                d = fmaf(d2, d2, d);
                // coeff = clip(1 - |KVAL - d*SIDIV|, 0, 1) == max(0.875 - 50 d, 0)
                float w = fmaxf(fmaf(d, -50.0f, 0.875f), 0.0f);
                den[p]  += w;
                num0[p]  = fmaf(w, va[j], num0[p]);
                num1[p]  = fmaf(w, vb[j], num1[p]);
            }
        }
    }

    // ---- normalize and store as FLOAT32, 16B coalesced per plane ----
    const int gy = y0 + ty;
    const int gx = x0 + bcol;

    float4 r0, r1;
    {
        float inv0 = 1.0f / den[0];
        float inv1 = 1.0f / den[1];
        float inv2 = 1.0f / den[2];
        float inv3 = 1.0f / den[3];
        r0 = make_float4(num0[0] * inv0, num0[1] * inv1, num0[2] * inv2, num0[3] * inv3);
        r1 = make_float4(num1[0] * inv0, num1[1] * inv1, num1[2] * inv2, num1[3] * inv3);
    }

    *reinterpret_cast<float4*>(out + (size_t)gy * IMG_W + gx) = r0;
    *reinterpret_cast<float4*>(out + (size_t)IMG_H * IMG_W + (size_t)gy * IMG_W + gx) = r1;
}

extern "C" void kernel_launch(void* const* d_in, const int* in_sizes, int n_in,
                              void* d_out, int out_size)
{
    // Bind by size: largest = template (3*H*W), second-largest = vector (2*H*W).
    int big0 = -1, big1 = -1;
    for (int i = 0; i < n_in; i++) {
        if (big0 < 0 || in_sizes[i] > in_sizes[big0]) { big1 = big0; big0 = i; }
        else if (big1 < 0 || in_sizes[i] > in_sizes[big1]) { big1 = i; }
    }
    if (big1 < 0) big1 = big0;

    const float* tpl = (const float*)d_in[big0];
    const float* vec = (const float*)d_in[big1];
    float* out = (float*)d_out;               // OUTPUT IS FLOAT32

    dim3 block(32, 8);
    dim3 grid(IMG_W / TILE_W, IMG_H / TILE_H);  // 15 x 135, exact tiling
    jbf_kernel<<<grid, block>>>(tpl, vec, out);
}